// round 6
// baseline (speedup 1.0000x reference)
#include <cuda_runtime.h>
#include <cuda_bf16.h>
#include <cstdint>
#include <cstddef>

// ---------------------------------------------------------------- constants
constexpr int cE = 8, cT = 4096, cD = 2048, cH = 1024;
constexpr size_t X_ELEMS = (size_t)cE * cT * cD;
constexpr size_t W_ELEMS = (size_t)cE * cD * cH;
constexpr size_t H_ELEMS = (size_t)cE * cT * cH;

// ---------------------------------------------------------------- scratch
__device__ __align__(16) __nv_bfloat16 g_x_hi[X_ELEMS];
__device__ __align__(16) __nv_bfloat16 g_x_lo[X_ELEMS];
__device__ __align__(16) __nv_bfloat16 g_w1t_hi[W_ELEMS];  // [E][H][D]
__device__ __align__(16) __nv_bfloat16 g_w1t_lo[W_ELEMS];
__device__ __align__(16) __nv_bfloat16 g_w3t_hi[W_ELEMS];  // [E][H][D]
__device__ __align__(16) __nv_bfloat16 g_w3t_lo[W_ELEMS];
__device__ __align__(16) __nv_bfloat16 g_w2t_hi[W_ELEMS];  // [E][D][H]
__device__ __align__(16) __nv_bfloat16 g_w2t_lo[W_ELEMS];
__device__ __align__(16) __nv_bfloat16 g_h_hi[H_ELEMS];    // [E][T][H]
__device__ __align__(16) __nv_bfloat16 g_h_lo[H_ELEMS];
__device__ __align__(16) float         g_G[H_ELEMS];       // [E][T][H] fp32

// ---------------------------------------------------------------- PTX helpers
__device__ __forceinline__ uint32_t smem_u32(const void* p) {
    return (uint32_t)__cvta_generic_to_shared(p);
}
__device__ __forceinline__ void cp16(uint32_t dst, const void* src) {
    asm volatile("cp.async.cg.shared.global [%0], [%1], 16;"
                 :: "r"(dst), "l"(src) : "memory");
}
__device__ __forceinline__ void cp_commit() {
    asm volatile("cp.async.commit_group;" ::: "memory");
}
template <int N> __device__ __forceinline__ void cp_wait() {
    asm volatile("cp.async.wait_group %0;" :: "n"(N) : "memory");
}
__device__ __forceinline__ void ldsm4(uint32_t* r, uint32_t addr) {
    asm volatile("ldmatrix.sync.aligned.m8n8.x4.shared.b16 {%0,%1,%2,%3}, [%4];"
                 : "=r"(r[0]), "=r"(r[1]), "=r"(r[2]), "=r"(r[3]) : "r"(addr));
}
__device__ __forceinline__ void mma16816(float* d, const uint32_t* a,
                                         uint32_t b0, uint32_t b1) {
    asm volatile(
        "mma.sync.aligned.m16n8k16.row.col.f32.bf16.bf16.f32 "
        "{%0,%1,%2,%3}, {%4,%5,%6,%7}, {%8,%9}, {%0,%1,%2,%3};"
        : "+f"(d[0]), "+f"(d[1]), "+f"(d[2]), "+f"(d[3])
        : "r"(a[0]), "r"(a[1]), "r"(a[2]), "r"(a[3]), "r"(b0), "r"(b1));
}
#define SWZ(o) ((o) ^ (((o) >> 3) & 0x70))

// ---------------------------------------------------------------- conversions
__device__ __forceinline__ void split_f32(float v, __nv_bfloat16& hi, __nv_bfloat16& lo) {
    hi = __float2bfloat16(v);
    lo = __float2bfloat16(v - __bfloat162float(hi));
}

__global__ void cvt_x_kernel(const float4* __restrict__ x) {
    size_t i = (size_t)blockIdx.x * blockDim.x + threadIdx.x;
    if (i >= X_ELEMS / 4) return;
    float4 v = x[i];
    __nv_bfloat16 h0, h1, h2, h3, l0, l1, l2, l3;
    split_f32(v.x, h0, l0); split_f32(v.y, h1, l1);
    split_f32(v.z, h2, l2); split_f32(v.w, h3, l3);
    uint2 oh, ol;
    oh.x = ((uint32_t)__bfloat16_as_ushort(h1) << 16) | __bfloat16_as_ushort(h0);
    oh.y = ((uint32_t)__bfloat16_as_ushort(h3) << 16) | __bfloat16_as_ushort(h2);
    ol.x = ((uint32_t)__bfloat16_as_ushort(l1) << 16) | __bfloat16_as_ushort(l0);
    ol.y = ((uint32_t)__bfloat16_as_ushort(l3) << 16) | __bfloat16_as_ushort(l2);
    ((uint2*)g_x_hi)[i] = oh;
    ((uint2*)g_x_lo)[i] = ol;
}

// transpose + split: w [E][R][C] f32 -> out [E][C][R] bf16 hi/lo
__global__ void cvt_tr_kernel(const float* __restrict__ w, int which, int R, int C) {
    __shared__ float tile[32][33];
    int e = blockIdx.z;
    int c0 = blockIdx.x * 32, r0 = blockIdx.y * 32;
    int tx = threadIdx.x, ty = threadIdx.y;
    const float* wp = w + (size_t)e * R * C;
#pragma unroll
    for (int i = ty; i < 32; i += 8)
        tile[i][tx] = wp[(size_t)(r0 + i) * C + c0 + tx];
    __syncthreads();
    __nv_bfloat16 *oh, *ol;
    if (which == 0)      { oh = g_w1t_hi; ol = g_w1t_lo; }
    else if (which == 1) { oh = g_w3t_hi; ol = g_w3t_lo; }
    else                 { oh = g_w2t_hi; ol = g_w2t_lo; }
    oh += (size_t)e * C * R;
    ol += (size_t)e * C * R;
#pragma unroll
    for (int i = ty; i < 32; i += 8) {
        __nv_bfloat16 h, l;
        split_f32(tile[tx][i], h, l);
        size_t o = (size_t)(c0 + i) * R + r0 + tx;
        oh[o] = h;
        ol[o] = l;
    }
}

// ---------------------------------------------------------------- GEMM
// C[128,128] = sum_k A[m,k]*B[n,k] via bf16x3 split on mma.sync m16n8k16.
// mode 0: write fp32 C to out. mode 1: h = silu(gaux)*C -> bf16 hi/lo.
constexpr int STAGES = 3;
constexpr int TILE_B = 128 * 128;            // 128 rows x 128 bytes (64 bf16)
constexpr int STAGE_B = 4 * TILE_B;          // Ahi, Alo, Bhi, Blo = 64 KB
constexpr int SMEM_REQ = STAGES * STAGE_B;   // 192 KB

__global__ void __launch_bounds__(256, 1) gemm_kernel(
    const __nv_bfloat16* __restrict__ Ahi, const __nv_bfloat16* __restrict__ Alo,
    const __nv_bfloat16* __restrict__ Bhi, const __nv_bfloat16* __restrict__ Blo,
    int K, int Ntot,
    float* __restrict__ out, const float* __restrict__ gaux,
    __nv_bfloat16* __restrict__ hhi, __nv_bfloat16* __restrict__ hlo, int mode)
{
    extern __shared__ __align__(1024) char smraw[];
    const uint32_t smem = smem_u32(smraw);
    const int tid = threadIdx.x;
    const int lane = tid & 31, w = tid >> 5;
    const int wm = (w >> 2) * 64;      // warp m-offset (2 m-warps)
    const int wn = (w & 3) * 32;       // warp n-offset (4 n-warps)
    const int n0 = blockIdx.x * 128, m0 = blockIdx.y * 128, e = blockIdx.z;

    // --- loader: thread t handles row t/2, 64-byte half t%2 of each tile
    const int lr = tid >> 1;
    const int lhB = (tid & 1) * 64;    // byte offset within 128B row
    const __nv_bfloat16* aH = Ahi + ((size_t)e * cT + m0 + lr) * K + (lhB >> 1);
    const __nv_bfloat16* aL = Alo + ((size_t)e * cT + m0 + lr) * K + (lhB >> 1);
    const __nv_bfloat16* bH = Bhi + ((size_t)e * Ntot + n0 + lr) * K + (lhB >> 1);
    const __nv_bfloat16* bL = Blo + ((size_t)e * Ntot + n0 + lr) * K + (lhB >> 1);
    const uint32_t lrow = (uint32_t)lr * 128u + (uint32_t)lhB;
    const int nK = K / 64;

    auto load_stage = [&](int s, int k) {
        uint32_t base = smem + s * STAGE_B;
        int k0 = k * 64;
#pragma unroll
        for (int j = 0; j < 4; j++) {
            uint32_t sw = SWZ(lrow + j * 16);
            cp16(base              + sw, aH + k0 + j * 8);
            cp16(base + TILE_B     + sw, aL + k0 + j * 8);
            cp16(base + 2 * TILE_B + sw, bH + k0 + j * 8);
            cp16(base + 3 * TILE_B + sw, bL + k0 + j * 8);
        }
    };

    // --- per-lane ldmatrix address components
    const uint32_t arow = (uint32_t)(lane & 15);            // A: rows 0..15
    const uint32_t akb  = (uint32_t)((lane >> 4) * 16);     // A: k-byte 0/16
    const uint32_t brow = (uint32_t)((lane & 7) + ((lane & 16) >> 1));  // B rows
    const uint32_t bkb  = (uint32_t)(((lane & 8) >> 3) * 16);

    float acc[4][4][4] = {};   // [mt][nt][c0..c3]

    load_stage(0, 0); cp_commit();
    load_stage(1, 1); cp_commit();
    load_stage(2, 2); cp_commit();

    for (int kk = 0; kk < nK; kk++) {
        int s = kk % STAGES;
        cp_wait<STAGES - 1>();
        __syncthreads();
        uint32_t base = smem + s * STAGE_B;
#pragma unroll
        for (int ks = 0; ks < 4; ks++) {
            uint32_t Ah[4][4], Al[4][4], Bh[2][4], Bl[2][4];
#pragma unroll
            for (int mt = 0; mt < 4; mt++) {
                uint32_t off = SWZ((uint32_t)(wm + mt * 16 + arow) * 128u + ks * 32 + akb);
                ldsm4(Ah[mt], base + off);
                ldsm4(Al[mt], base + TILE_B + off);
            }
#pragma unroll
            for (int np = 0; np < 2; np++) {
                uint32_t off = SWZ((uint32_t)(wn + np * 16 + brow) * 128u + ks * 32 + bkb);
                ldsm4(Bh[np], base + 2 * TILE_B + off);
                ldsm4(Bl[np], base + 3 * TILE_B + off);
            }
#pragma unroll
            for (int mt = 0; mt < 4; mt++)
#pragma unroll
                for (int nt = 0; nt < 4; nt++) {
                    int np = nt >> 1, ss = (nt & 1) * 2;
                    mma16816(acc[mt][nt], Ah[mt], Bh[np][ss], Bh[np][ss + 1]);
                    mma16816(acc[mt][nt], Al[mt], Bh[np][ss], Bh[np][ss + 1]);
                    mma16816(acc[mt][nt], Ah[mt], Bl[np][ss], Bl[np][ss + 1]);
                }
        }
        __syncthreads();
        if (kk + STAGES < nK) load_stage(s, kk + STAGES);
        cp_commit();   // uniform group accounting (may be empty)
    }

    // --- epilogue
#pragma unroll
    for (int mt = 0; mt < 4; mt++) {
#pragma unroll
        for (int p = 0; p < 2; p++) {
            int lrow2 = wm + mt * 16 + (lane >> 2) + p * 8;
            size_t gr = ((size_t)e * cT + m0 + lrow2) * (size_t)Ntot;
#pragma unroll
            for (int nt = 0; nt < 4; nt++) {
                int lcol = wn + nt * 8 + (lane & 3) * 2;
                size_t idx = gr + n0 + lcol;
                float v0 = acc[mt][nt][p * 2], v1 = acc[mt][nt][p * 2 + 1];
                if (mode == 0) {
                    *(float2*)(out + idx) = make_float2(v0, v1);
                } else {
                    float2 g = *(const float2*)(gaux + idx);
                    float h0 = v0 * g.x / (1.0f + __expf(-g.x));
                    float h1 = v1 * g.y / (1.0f + __expf(-g.y));
                    __nv_bfloat16 h0h, h0l, h1h, h1l;
                    split_f32(h0, h0h, h0l);
                    split_f32(h1, h1h, h1l);
                    __nv_bfloat162 vh; vh.x = h0h; vh.y = h1h;
                    __nv_bfloat162 vl; vl.x = h0l; vl.y = h1l;
                    *(__nv_bfloat162*)(hhi + idx) = vh;
                    *(__nv_bfloat162*)(hlo + idx) = vl;
                }
            }
        }
    }
}

// ---------------------------------------------------------------- host
static inline void* symaddr(const void* s) {
    void* p = nullptr;
    cudaGetSymbolAddress(&p, s);
    return p;
}

extern "C" void kernel_launch(void* const* d_in, const int* in_sizes, int n_in,
                              void* d_out, int out_size) {
    (void)in_sizes; (void)n_in; (void)out_size;
    const float* x  = (const float*)d_in[0];
    const float* w1 = (const float*)d_in[1];
    const float* w2 = (const float*)d_in[2];
    const float* w3 = (const float*)d_in[3];
    float* out = (float*)d_out;

    __nv_bfloat16* xhi = (__nv_bfloat16*)symaddr(g_x_hi);
    __nv_bfloat16* xlo = (__nv_bfloat16*)symaddr(g_x_lo);
    __nv_bfloat16* w1h = (__nv_bfloat16*)symaddr(g_w1t_hi);
    __nv_bfloat16* w1l = (__nv_bfloat16*)symaddr(g_w1t_lo);
    __nv_bfloat16* w3h = (__nv_bfloat16*)symaddr(g_w3t_hi);
    __nv_bfloat16* w3l = (__nv_bfloat16*)symaddr(g_w3t_lo);
    __nv_bfloat16* w2h = (__nv_bfloat16*)symaddr(g_w2t_hi);
    __nv_bfloat16* w2l = (__nv_bfloat16*)symaddr(g_w2t_lo);
    __nv_bfloat16* hhi = (__nv_bfloat16*)symaddr(g_h_hi);
    __nv_bfloat16* hlo = (__nv_bfloat16*)symaddr(g_h_lo);
    float*         G   = (float*)symaddr(g_G);

    cudaFuncSetAttribute(gemm_kernel, cudaFuncAttributeMaxDynamicSharedMemorySize, SMEM_REQ);

    // 1) split x into bf16 hi/lo
    cvt_x_kernel<<<(int)(X_ELEMS / 4 / 256), 256>>>((const float4*)x);
    // 2-4) transpose + split weights (B operands K-major)
    cvt_tr_kernel<<<dim3(cH / 32, cD / 32, cE), dim3(32, 8)>>>(w1, 0, cD, cH);
    cvt_tr_kernel<<<dim3(cH / 32, cD / 32, cE), dim3(32, 8)>>>(w3, 1, cD, cH);
    cvt_tr_kernel<<<dim3(cD / 32, cH / 32, cE), dim3(32, 8)>>>(w2, 2, cH, cD);
    // 5) G = x @ w1 (fp32 scratch)
    gemm_kernel<<<dim3(cH / 128, cT / 128, cE), 256, SMEM_REQ>>>(
        xhi, xlo, w1h, w1l, cD, cH, G, nullptr, nullptr, nullptr, 0);
    // 6) U = x @ w3, fused SwiGLU: h = silu(G) * U -> bf16 hi/lo
    gemm_kernel<<<dim3(cH / 128, cT / 128, cE), 256, SMEM_REQ>>>(
        xhi, xlo, w3h, w3l, cD, cH, nullptr, G, hhi, hlo, 1);
    // 7) out = h @ w2 (fp32 final)
    gemm_kernel<<<dim3(cD / 128, cT / 128, cE), 256, SMEM_REQ>>>(
        hhi, hlo, w2h, w2l, cH, cD, out, nullptr, nullptr, nullptr, 0);
}

// round 7
// speedup vs baseline: 1.5827x; 1.5827x over previous
#include <cuda_runtime.h>
#include <cuda_fp16.h>
#include <cstdint>
#include <cstddef>

// ---------------------------------------------------------------- constants
constexpr int cE = 8, cT = 4096, cD = 2048, cH = 1024;
constexpr size_t X_ELEMS = (size_t)cE * cT * cD;
constexpr size_t W_ELEMS = (size_t)cE * cD * cH;
constexpr size_t H_ELEMS = (size_t)cE * cT * cH;

// ---------------------------------------------------------------- scratch
__device__ __align__(16) __half g_x_hi[X_ELEMS];
__device__ __align__(16) __half g_x_lo[X_ELEMS];
__device__ __align__(16) __half g_w1t[W_ELEMS];   // [E][H][D] fp16(w1^T)
__device__ __align__(16) __half g_w3t[W_ELEMS];   // [E][H][D] fp16(w3^T)
__device__ __align__(16) __half g_w2t[W_ELEMS];   // [E][D][H] fp16(w2^T)
__device__ __align__(16) __half g_h_hi[H_ELEMS];  // [E][T][H]
__device__ __align__(16) __half g_h_lo[H_ELEMS];

// ---------------------------------------------------------------- PTX helpers
__device__ __forceinline__ uint32_t smem_u32(const void* p) {
    return (uint32_t)__cvta_generic_to_shared(p);
}
__device__ __forceinline__ void cp16(uint32_t dst, const void* src) {
    asm volatile("cp.async.cg.shared.global [%0], [%1], 16;"
                 :: "r"(dst), "l"(src) : "memory");
}
__device__ __forceinline__ void cp_commit() {
    asm volatile("cp.async.commit_group;" ::: "memory");
}
template <int N> __device__ __forceinline__ void cp_wait() {
    asm volatile("cp.async.wait_group %0;" :: "n"(N) : "memory");
}
__device__ __forceinline__ void ldsm4(uint32_t* r, uint32_t addr) {
    asm volatile("ldmatrix.sync.aligned.m8n8.x4.shared.b16 {%0,%1,%2,%3}, [%4];"
                 : "=r"(r[0]), "=r"(r[1]), "=r"(r[2]), "=r"(r[3]) : "r"(addr));
}
__device__ __forceinline__ void mma16816(float* d, const uint32_t* a,
                                         uint32_t b0, uint32_t b1) {
    asm volatile(
        "mma.sync.aligned.m16n8k16.row.col.f32.f16.f16.f32 "
        "{%0,%1,%2,%3}, {%4,%5,%6,%7}, {%8,%9}, {%0,%1,%2,%3};"
        : "+f"(d[0]), "+f"(d[1]), "+f"(d[2]), "+f"(d[3])
        : "r"(a[0]), "r"(a[1]), "r"(a[2]), "r"(a[3]), "r"(b0), "r"(b1));
}
#define SWZ(o) ((o) ^ (((o) >> 3) & 0x70))

// ---------------------------------------------------------------- conversions
__device__ __forceinline__ void split_f32h(float v, __half& hi, __half& lo) {
    hi = __float2half(v);
    lo = __float2half(v - __half2float(hi));
}

__global__ void cvt_x_kernel(const float4* __restrict__ x) {
    size_t i = (size_t)blockIdx.x * blockDim.x + threadIdx.x;
    if (i >= X_ELEMS / 4) return;
    float4 v = x[i];
    __half h0, h1, h2, h3, l0, l1, l2, l3;
    split_f32h(v.x, h0, l0); split_f32h(v.y, h1, l1);
    split_f32h(v.z, h2, l2); split_f32h(v.w, h3, l3);
    uint2 oh, ol;
    oh.x = ((uint32_t)__half_as_ushort(h1) << 16) | __half_as_ushort(h0);
    oh.y = ((uint32_t)__half_as_ushort(h3) << 16) | __half_as_ushort(h2);
    ol.x = ((uint32_t)__half_as_ushort(l1) << 16) | __half_as_ushort(l0);
    ol.y = ((uint32_t)__half_as_ushort(l3) << 16) | __half_as_ushort(l2);
    ((uint2*)g_x_hi)[i] = oh;
    ((uint2*)g_x_lo)[i] = ol;
}

// transpose: w [E][R][C] f32 -> out [E][C][R] fp16 (hi only, B operands)
__global__ void cvt_tr_kernel(const float* __restrict__ w, int which, int R, int C) {
    __shared__ float tile[32][33];
    int e = blockIdx.z;
    int c0 = blockIdx.x * 32, r0 = blockIdx.y * 32;
    int tx = threadIdx.x, ty = threadIdx.y;
    const float* wp = w + (size_t)e * R * C;
#pragma unroll
    for (int i = ty; i < 32; i += 8)
        tile[i][tx] = wp[(size_t)(r0 + i) * C + c0 + tx];
    __syncthreads();
    __half* oh = (which == 0) ? g_w1t : (which == 1) ? g_w3t : g_w2t;
    oh += (size_t)e * C * R;
#pragma unroll
    for (int i = ty; i < 32; i += 8)
        oh[(size_t)(c0 + i) * R + r0 + tx] = __float2half(tile[tx][i]);
}

// ---------------------------------------------------------------- fused dual GEMM
// G = x@w1, U = x@w3 (fp16x2 split on A, fp16 B), h = silu(G)*U -> fp16 hi/lo.
constexpr int TILE_B = 128 * 128;            // 128 rows x 128 bytes (64 halfs)
constexpr int STAGES_F = 3;
constexpr int STAGE_F_B = 4 * TILE_B;        // Ahi, Alo, B1, B3 = 64 KB
constexpr int SMEM_F = STAGES_F * STAGE_F_B; // 192 KB

__global__ void __launch_bounds__(256, 1) dual_gemm_kernel(
    const __half* __restrict__ Ahi, const __half* __restrict__ Alo,
    const __half* __restrict__ B1, const __half* __restrict__ B3,
    __half* __restrict__ hhi, __half* __restrict__ hlo)
{
    constexpr int K = cD, Ntot = cH;
    extern __shared__ __align__(1024) char smraw[];
    const uint32_t smem = smem_u32(smraw);
    const int tid = threadIdx.x;
    const int lane = tid & 31, w = tid >> 5;
    const int wm = (w >> 2) * 64;
    const int wn = (w & 3) * 32;
    const int n0 = blockIdx.x * 128, m0 = blockIdx.y * 128, e = blockIdx.z;

    const int lr = tid >> 1;
    const int lhB = (tid & 1) * 64;
    const __half* aH = Ahi + ((size_t)e * cT + m0 + lr) * K + (lhB >> 1);
    const __half* aL = Alo + ((size_t)e * cT + m0 + lr) * K + (lhB >> 1);
    const __half* b1 = B1 + ((size_t)e * Ntot + n0 + lr) * K + (lhB >> 1);
    const __half* b3 = B3 + ((size_t)e * Ntot + n0 + lr) * K + (lhB >> 1);
    const uint32_t lrow = (uint32_t)lr * 128u + (uint32_t)lhB;
    const int nK = K / 64;

    auto load_stage = [&](int s, int k) {
        uint32_t base = smem + s * STAGE_F_B;
        int k0 = k * 64;
#pragma unroll
        for (int j = 0; j < 4; j++) {
            uint32_t sw = SWZ(lrow + j * 16);
            cp16(base              + sw, aH + k0 + j * 8);
            cp16(base + TILE_B     + sw, aL + k0 + j * 8);
            cp16(base + 2 * TILE_B + sw, b1 + k0 + j * 8);
            cp16(base + 3 * TILE_B + sw, b3 + k0 + j * 8);
        }
    };

    const uint32_t arow = (uint32_t)(lane & 15);
    const uint32_t akb  = (uint32_t)((lane >> 4) * 16);
    const uint32_t brow = (uint32_t)((lane & 7) + ((lane & 16) >> 1));
    const uint32_t bkb  = (uint32_t)(((lane & 8) >> 3) * 16);

    float accG[4][4][4] = {};
    float accU[4][4][4] = {};

    load_stage(0, 0); cp_commit();
    load_stage(1, 1); cp_commit();
    load_stage(2, 2); cp_commit();

    for (int kk = 0; kk < nK; kk++) {
        int s = kk % STAGES_F;
        cp_wait<STAGES_F - 1>();
        __syncthreads();
        uint32_t base = smem + s * STAGE_F_B;
#pragma unroll
        for (int ks = 0; ks < 4; ks++) {
            uint32_t Ah[4][4], Al[4][4], Bf[2][4];
#pragma unroll
            for (int mt = 0; mt < 4; mt++) {
                uint32_t off = SWZ((uint32_t)(wm + mt * 16 + arow) * 128u + ks * 32 + akb);
                ldsm4(Ah[mt], base + off);
                ldsm4(Al[mt], base + TILE_B + off);
            }
            // --- GEMM1 (w1): load B1 frags, 32 mma
#pragma unroll
            for (int np = 0; np < 2; np++) {
                uint32_t off = SWZ((uint32_t)(wn + np * 16 + brow) * 128u + ks * 32 + bkb);
                ldsm4(Bf[np], base + 2 * TILE_B + off);
            }
#pragma unroll
            for (int mt = 0; mt < 4; mt++)
#pragma unroll
                for (int nt = 0; nt < 4; nt++) {
                    int np = nt >> 1, ss = (nt & 1) * 2;
                    mma16816(accG[mt][nt], Ah[mt], Bf[np][ss], Bf[np][ss + 1]);
                    mma16816(accG[mt][nt], Al[mt], Bf[np][ss], Bf[np][ss + 1]);
                }
            // --- GEMM3 path (w3): reuse B frag regs, 32 mma
#pragma unroll
            for (int np = 0; np < 2; np++) {
                uint32_t off = SWZ((uint32_t)(wn + np * 16 + brow) * 128u + ks * 32 + bkb);
                ldsm4(Bf[np], base + 3 * TILE_B + off);
            }
#pragma unroll
            for (int mt = 0; mt < 4; mt++)
#pragma unroll
                for (int nt = 0; nt < 4; nt++) {
                    int np = nt >> 1, ss = (nt & 1) * 2;
                    mma16816(accU[mt][nt], Ah[mt], Bf[np][ss], Bf[np][ss + 1]);
                    mma16816(accU[mt][nt], Al[mt], Bf[np][ss], Bf[np][ss + 1]);
                }
        }
        __syncthreads();
        if (kk + STAGES_F < nK) load_stage(s, kk + STAGES_F);
        cp_commit();
    }

    // --- epilogue: h = silu(G) * U, split to fp16 hi/lo
#pragma unroll
    for (int mt = 0; mt < 4; mt++) {
#pragma unroll
        for (int p = 0; p < 2; p++) {
            int lrow2 = wm + mt * 16 + (lane >> 2) + p * 8;
            size_t gr = ((size_t)e * cT + m0 + lrow2) * (size_t)Ntot;
#pragma unroll
            for (int nt = 0; nt < 4; nt++) {
                int lcol = wn + nt * 8 + (lane & 3) * 2;
                size_t idx = gr + n0 + lcol;
                float gv0 = accG[mt][nt][p * 2], gv1 = accG[mt][nt][p * 2 + 1];
                float uv0 = accU[mt][nt][p * 2], uv1 = accU[mt][nt][p * 2 + 1];
                float h0 = uv0 * gv0 / (1.0f + __expf(-gv0));
                float h1 = uv1 * gv1 / (1.0f + __expf(-gv1));
                __half h0h, h0l, h1h, h1l;
                split_f32h(h0, h0h, h0l);
                split_f32h(h1, h1h, h1l);
                __half2 vh; vh.x = h0h; vh.y = h1h;
                __half2 vl; vl.x = h0l; vl.y = h1l;
                *(__half2*)(hhi + idx) = vh;
                *(__half2*)(hlo + idx) = vl;
            }
        }
    }
}

// ---------------------------------------------------------------- out GEMM
// out = h @ w2, fp16x2 split on A (h), fp16 B (w2), fp32 out.
constexpr int STAGES_O = 4;
constexpr int STAGE_O_B = 3 * TILE_B;        // Ahi, Alo, B = 48 KB
constexpr int SMEM_O = STAGES_O * STAGE_O_B; // 192 KB

__global__ void __launch_bounds__(256, 1) out_gemm_kernel(
    const __half* __restrict__ Ahi, const __half* __restrict__ Alo,
    const __half* __restrict__ B, float* __restrict__ out)
{
    constexpr int K = cH, Ntot = cD;
    extern __shared__ __align__(1024) char smraw[];
    const uint32_t smem = smem_u32(smraw);
    const int tid = threadIdx.x;
    const int lane = tid & 31, w = tid >> 5;
    const int wm = (w >> 2) * 64;
    const int wn = (w & 3) * 32;
    const int n0 = blockIdx.x * 128, m0 = blockIdx.y * 128, e = blockIdx.z;

    const int lr = tid >> 1;
    const int lhB = (tid & 1) * 64;
    const __half* aH = Ahi + ((size_t)e * cT + m0 + lr) * K + (lhB >> 1);
    const __half* aL = Alo + ((size_t)e * cT + m0 + lr) * K + (lhB >> 1);
    const __half* bH = B + ((size_t)e * Ntot + n0 + lr) * K + (lhB >> 1);
    const uint32_t lrow = (uint32_t)lr * 128u + (uint32_t)lhB;
    const int nK = K / 64;

    auto load_stage = [&](int s, int k) {
        uint32_t base = smem + s * STAGE_O_B;
        int k0 = k * 64;
#pragma unroll
        for (int j = 0; j < 4; j++) {
            uint32_t sw = SWZ(lrow + j * 16);
            cp16(base              + sw, aH + k0 + j * 8);
            cp16(base + TILE_B     + sw, aL + k0 + j * 8);
            cp16(base + 2 * TILE_B + sw, bH + k0 + j * 8);
        }
    };

    const uint32_t arow = (uint32_t)(lane & 15);
    const uint32_t akb  = (uint32_t)((lane >> 4) * 16);
    const uint32_t brow = (uint32_t)((lane & 7) + ((lane & 16) >> 1));
    const uint32_t bkb  = (uint32_t)(((lane & 8) >> 3) * 16);

    float acc[4][4][4] = {};

    load_stage(0, 0); cp_commit();
    load_stage(1, 1); cp_commit();
    load_stage(2, 2); cp_commit();
    load_stage(3, 3); cp_commit();

    for (int kk = 0; kk < nK; kk++) {
        int s = kk % STAGES_O;
        cp_wait<STAGES_O - 1>();
        __syncthreads();
        uint32_t base = smem + s * STAGE_O_B;
#pragma unroll
        for (int ks = 0; ks < 4; ks++) {
            uint32_t Ah[4][4], Al[4][4], Bh[2][4];
#pragma unroll
            for (int mt = 0; mt < 4; mt++) {
                uint32_t off = SWZ((uint32_t)(wm + mt * 16 + arow) * 128u + ks * 32 + akb);
                ldsm4(Ah[mt], base + off);
                ldsm4(Al[mt], base + TILE_B + off);
            }
#pragma unroll
            for (int np = 0; np < 2; np++) {
                uint32_t off = SWZ((uint32_t)(wn + np * 16 + brow) * 128u + ks * 32 + bkb);
                ldsm4(Bh[np], base + 2 * TILE_B + off);
            }
#pragma unroll
            for (int mt = 0; mt < 4; mt++)
#pragma unroll
                for (int nt = 0; nt < 4; nt++) {
                    int np = nt >> 1, ss = (nt & 1) * 2;
                    mma16816(acc[mt][nt], Ah[mt], Bh[np][ss], Bh[np][ss + 1]);
                    mma16816(acc[mt][nt], Al[mt], Bh[np][ss], Bh[np][ss + 1]);
                }
        }
        __syncthreads();
        if (kk + STAGES_O < nK) load_stage(s, kk + STAGES_O);
        cp_commit();
    }

#pragma unroll
    for (int mt = 0; mt < 4; mt++) {
#pragma unroll
        for (int p = 0; p < 2; p++) {
            int lrow2 = wm + mt * 16 + (lane >> 2) + p * 8;
            size_t gr = ((size_t)e * cT + m0 + lrow2) * (size_t)Ntot;
#pragma unroll
            for (int nt = 0; nt < 4; nt++) {
                int lcol = wn + nt * 8 + (lane & 3) * 2;
                *(float2*)(out + gr + n0 + lcol) =
                    make_float2(acc[mt][nt][p * 2], acc[mt][nt][p * 2 + 1]);
            }
        }
    }
}

// ---------------------------------------------------------------- host
static inline void* symaddr(const void* s) {
    void* p = nullptr;
    cudaGetSymbolAddress(&p, s);
    return p;
}

extern "C" void kernel_launch(void* const* d_in, const int* in_sizes, int n_in,
                              void* d_out, int out_size) {
    (void)in_sizes; (void)n_in; (void)out_size;
    const float* x  = (const float*)d_in[0];
    const float* w1 = (const float*)d_in[1];
    const float* w2 = (const float*)d_in[2];
    const float* w3 = (const float*)d_in[3];
    float* out = (float*)d_out;

    __half* xhi = (__half*)symaddr(g_x_hi);
    __half* xlo = (__half*)symaddr(g_x_lo);
    __half* w1t = (__half*)symaddr(g_w1t);
    __half* w3t = (__half*)symaddr(g_w3t);
    __half* w2t = (__half*)symaddr(g_w2t);
    __half* hhi = (__half*)symaddr(g_h_hi);
    __half* hlo = (__half*)symaddr(g_h_lo);

    cudaFuncSetAttribute(dual_gemm_kernel, cudaFuncAttributeMaxDynamicSharedMemorySize, SMEM_F);
    cudaFuncSetAttribute(out_gemm_kernel, cudaFuncAttributeMaxDynamicSharedMemorySize, SMEM_O);

    // 1) split x into fp16 hi/lo
    cvt_x_kernel<<<(int)(X_ELEMS / 4 / 256), 256>>>((const float4*)x);
    // 2-4) transpose weights to K-major fp16
    cvt_tr_kernel<<<dim3(cH / 32, cD / 32, cE), dim3(32, 8)>>>(w1, 0, cD, cH);
    cvt_tr_kernel<<<dim3(cH / 32, cD / 32, cE), dim3(32, 8)>>>(w3, 1, cD, cH);
    cvt_tr_kernel<<<dim3(cD / 32, cH / 32, cE), dim3(32, 8)>>>(w2, 2, cH, cD);
    // 5) fused: G = x@w1, U = x@w3, h = silu(G)*U -> fp16 hi/lo
    dual_gemm_kernel<<<dim3(cH / 128, cT / 128, cE), 256, SMEM_F>>>(
        xhi, xlo, w1t, w3t, hhi, hlo);
    // 6) out = h @ w2 (fp32)
    out_gemm_kernel<<<dim3(cD / 128, cT / 128, cE), 256, SMEM_O>>>(
        hhi, hlo, w2t, out);
}

// round 8
// speedup vs baseline: 2.0428x; 1.2907x over previous
#include <cuda_runtime.h>
#include <cuda_fp16.h>
#include <cstdint>
#include <cstddef>

// ---------------------------------------------------------------- constants
constexpr int cE = 8, cT = 4096, cD = 2048, cH = 1024;
constexpr size_t X_ELEMS = (size_t)cE * cT * cD;
constexpr size_t W_ELEMS = (size_t)cE * cD * cH;
constexpr size_t H_ELEMS = (size_t)cE * cT * cH;

// ---------------------------------------------------------------- scratch
__device__ __align__(16) __half g_x_hi[X_ELEMS];
__device__ __align__(16) __half g_x_lo[X_ELEMS];
__device__ __align__(16) __half g_w1t[W_ELEMS];   // [E][H][D] fp16(w1^T)
__device__ __align__(16) __half g_w3t[W_ELEMS];   // [E][H][D] fp16(w3^T)
__device__ __align__(16) __half g_w2t[W_ELEMS];   // [E][D][H] fp16(w2^T)
__device__ __align__(16) __half g_h[H_ELEMS];     // [E][T][H] fp16(h)

// ---------------------------------------------------------------- PTX helpers
__device__ __forceinline__ uint32_t smem_u32(const void* p) {
    return (uint32_t)__cvta_generic_to_shared(p);
}
__device__ __forceinline__ void cp16(uint32_t dst, const void* src) {
    asm volatile("cp.async.cg.shared.global [%0], [%1], 16;"
                 :: "r"(dst), "l"(src) : "memory");
}
__device__ __forceinline__ void cp_commit() {
    asm volatile("cp.async.commit_group;" ::: "memory");
}
template <int N> __device__ __forceinline__ void cp_wait() {
    asm volatile("cp.async.wait_group %0;" :: "n"(N) : "memory");
}
__device__ __forceinline__ void ldsm4(uint32_t* r, uint32_t addr) {
    asm volatile("ldmatrix.sync.aligned.m8n8.x4.shared.b16 {%0,%1,%2,%3}, [%4];"
                 : "=r"(r[0]), "=r"(r[1]), "=r"(r[2]), "=r"(r[3]) : "r"(addr));
}
__device__ __forceinline__ void mma16816(float* d, const uint32_t* a,
                                         uint32_t b0, uint32_t b1) {
    asm volatile(
        "mma.sync.aligned.m16n8k16.row.col.f32.f16.f16.f32 "
        "{%0,%1,%2,%3}, {%4,%5,%6,%7}, {%8,%9}, {%0,%1,%2,%3};"
        : "+f"(d[0]), "+f"(d[1]), "+f"(d[2]), "+f"(d[3])
        : "r"(a[0]), "r"(a[1]), "r"(a[2]), "r"(a[3]), "r"(b0), "r"(b1));
}
#define SWZ(o) ((o) ^ (((o) >> 3) & 0x70))

// ---------------------------------------------------------------- conversions
__device__ __forceinline__ void split_f32h(float v, __half& hi, __half& lo) {
    hi = __float2half(v);
    lo = __float2half(v - __half2float(hi));
}

__global__ void cvt_x_kernel(const float4* __restrict__ x) {
    size_t i = (size_t)blockIdx.x * blockDim.x + threadIdx.x;
    if (i >= X_ELEMS / 4) return;
    float4 v = x[i];
    __half h0, h1, h2, h3, l0, l1, l2, l3;
    split_f32h(v.x, h0, l0); split_f32h(v.y, h1, l1);
    split_f32h(v.z, h2, l2); split_f32h(v.w, h3, l3);
    uint2 oh, ol;
    oh.x = ((uint32_t)__half_as_ushort(h1) << 16) | __half_as_ushort(h0);
    oh.y = ((uint32_t)__half_as_ushort(h3) << 16) | __half_as_ushort(h2);
    ol.x = ((uint32_t)__half_as_ushort(l1) << 16) | __half_as_ushort(l0);
    ol.y = ((uint32_t)__half_as_ushort(l3) << 16) | __half_as_ushort(l2);
    ((uint2*)g_x_hi)[i] = oh;
    ((uint2*)g_x_lo)[i] = ol;
}

// transpose: w [E][R][C] f32 -> out [E][C][R] fp16
__global__ void cvt_tr_kernel(const float* __restrict__ w, int which, int R, int C) {
    __shared__ float tile[32][33];
    int e = blockIdx.z;
    int c0 = blockIdx.x * 32, r0 = blockIdx.y * 32;
    int tx = threadIdx.x, ty = threadIdx.y;
    const float* wp = w + (size_t)e * R * C;
#pragma unroll
    for (int i = ty; i < 32; i += 8)
        tile[i][tx] = wp[(size_t)(r0 + i) * C + c0 + tx];
    __syncthreads();
    __half* oh = (which == 0) ? g_w1t : (which == 1) ? g_w3t : g_w2t;
    oh += (size_t)e * C * R;
#pragma unroll
    for (int i = ty; i < 32; i += 8)
        oh[(size_t)(c0 + i) * R + r0 + tx] = __float2half(tile[tx][i]);
}

// ---------------------------------------------------------------- fused dual GEMM
// G = x@w1 (2-product: xhi+xlo), U = x@w3 (1-product: xhi only),
// h = silu(G)*U -> single fp16.
constexpr int TILE_B = 128 * 128;            // 128 rows x 128 bytes (64 halfs)
constexpr int STAGES_F = 3;
constexpr int STAGE_F_B = 4 * TILE_B;        // Ahi, Alo, B1, B3 = 64 KB
constexpr int SMEM_F = STAGES_F * STAGE_F_B; // 192 KB

__global__ void __launch_bounds__(256, 1) dual_gemm_kernel(
    const __half* __restrict__ Ahi, const __half* __restrict__ Alo,
    const __half* __restrict__ B1, const __half* __restrict__ B3,
    __half* __restrict__ hout)
{
    constexpr int K = cD, Ntot = cH;
    extern __shared__ __align__(1024) char smraw[];
    const uint32_t smem = smem_u32(smraw);
    const int tid = threadIdx.x;
    const int lane = tid & 31, w = tid >> 5;
    const int wm = (w >> 2) * 64;
    const int wn = (w & 3) * 32;
    const int n0 = blockIdx.x * 128, m0 = blockIdx.y * 128, e = blockIdx.z;

    const int lr = tid >> 1;
    const int lhB = (tid & 1) * 64;
    const __half* aH = Ahi + ((size_t)e * cT + m0 + lr) * K + (lhB >> 1);
    const __half* aL = Alo + ((size_t)e * cT + m0 + lr) * K + (lhB >> 1);
    const __half* b1 = B1 + ((size_t)e * Ntot + n0 + lr) * K + (lhB >> 1);
    const __half* b3 = B3 + ((size_t)e * Ntot + n0 + lr) * K + (lhB >> 1);
    const uint32_t lrow = (uint32_t)lr * 128u + (uint32_t)lhB;
    const int nK = K / 64;

    auto load_stage = [&](int s, int k) {
        uint32_t base = smem + s * STAGE_F_B;
        int k0 = k * 64;
#pragma unroll
        for (int j = 0; j < 4; j++) {
            uint32_t sw = SWZ(lrow + j * 16);
            cp16(base              + sw, aH + k0 + j * 8);
            cp16(base + TILE_B     + sw, aL + k0 + j * 8);
            cp16(base + 2 * TILE_B + sw, b1 + k0 + j * 8);
            cp16(base + 3 * TILE_B + sw, b3 + k0 + j * 8);
        }
    };

    const uint32_t arow = (uint32_t)(lane & 15);
    const uint32_t akb  = (uint32_t)((lane >> 4) * 16);
    const uint32_t brow = (uint32_t)((lane & 7) + ((lane & 16) >> 1));
    const uint32_t bkb  = (uint32_t)(((lane & 8) >> 3) * 16);

    float accG[4][4][4] = {};
    float accU[4][4][4] = {};

    load_stage(0, 0); cp_commit();
    load_stage(1, 1); cp_commit();
    load_stage(2, 2); cp_commit();

    for (int kk = 0; kk < nK; kk++) {
        int s = kk % STAGES_F;
        cp_wait<STAGES_F - 1>();
        __syncthreads();
        uint32_t base = smem + s * STAGE_F_B;
#pragma unroll
        for (int ks = 0; ks < 4; ks++) {
            uint32_t Ah[4][4], Al[4][4], Bf[2][4];
#pragma unroll
            for (int mt = 0; mt < 4; mt++) {
                uint32_t off = SWZ((uint32_t)(wm + mt * 16 + arow) * 128u + ks * 32 + akb);
                ldsm4(Ah[mt], base + off);
                ldsm4(Al[mt], base + TILE_B + off);
            }
            // --- G path (w1): 2 products
#pragma unroll
            for (int np = 0; np < 2; np++) {
                uint32_t off = SWZ((uint32_t)(wn + np * 16 + brow) * 128u + ks * 32 + bkb);
                ldsm4(Bf[np], base + 2 * TILE_B + off);
            }
#pragma unroll
            for (int mt = 0; mt < 4; mt++)
#pragma unroll
                for (int nt = 0; nt < 4; nt++) {
                    int np = nt >> 1, ss = (nt & 1) * 2;
                    mma16816(accG[mt][nt], Ah[mt], Bf[np][ss], Bf[np][ss + 1]);
                    mma16816(accG[mt][nt], Al[mt], Bf[np][ss], Bf[np][ss + 1]);
                }
            // --- U path (w3): 1 product (hi only)
#pragma unroll
            for (int np = 0; np < 2; np++) {
                uint32_t off = SWZ((uint32_t)(wn + np * 16 + brow) * 128u + ks * 32 + bkb);
                ldsm4(Bf[np], base + 3 * TILE_B + off);
            }
#pragma unroll
            for (int mt = 0; mt < 4; mt++)
#pragma unroll
                for (int nt = 0; nt < 4; nt++) {
                    int np = nt >> 1, ss = (nt & 1) * 2;
                    mma16816(accU[mt][nt], Ah[mt], Bf[np][ss], Bf[np][ss + 1]);
                }
        }
        __syncthreads();
        if (kk + STAGES_F < nK) load_stage(s, kk + STAGES_F);
        cp_commit();
    }

    // --- epilogue: h = silu(G) * U -> fp16
#pragma unroll
    for (int mt = 0; mt < 4; mt++) {
#pragma unroll
        for (int p = 0; p < 2; p++) {
            int lrow2 = wm + mt * 16 + (lane >> 2) + p * 8;
            size_t gr = ((size_t)e * cT + m0 + lrow2) * (size_t)Ntot;
#pragma unroll
            for (int nt = 0; nt < 4; nt++) {
                int lcol = wn + nt * 8 + (lane & 3) * 2;
                size_t idx = gr + n0 + lcol;
                float gv0 = accG[mt][nt][p * 2], gv1 = accG[mt][nt][p * 2 + 1];
                float uv0 = accU[mt][nt][p * 2], uv1 = accU[mt][nt][p * 2 + 1];
                float h0 = uv0 * gv0 / (1.0f + __expf(-gv0));
                float h1 = uv1 * gv1 / (1.0f + __expf(-gv1));
                __half2 vh;
                vh.x = __float2half(h0);
                vh.y = __float2half(h1);
                *(__half2*)(hout + idx) = vh;
            }
        }
    }
}

// ---------------------------------------------------------------- out GEMM
// out = h @ w2, single fp16 product, fp32 out. 6-stage pipeline.
constexpr int STAGES_O = 6;
constexpr int STAGE_O_B = 2 * TILE_B;        // A, B = 32 KB
constexpr int SMEM_O = STAGES_O * STAGE_O_B; // 192 KB

__global__ void __launch_bounds__(256, 1) out_gemm_kernel(
    const __half* __restrict__ A, const __half* __restrict__ B,
    float* __restrict__ out)
{
    constexpr int K = cH, Ntot = cD;
    extern __shared__ __align__(1024) char smraw[];
    const uint32_t smem = smem_u32(smraw);
    const int tid = threadIdx.x;
    const int lane = tid & 31, w = tid >> 5;
    const int wm = (w >> 2) * 64;
    const int wn = (w & 3) * 32;
    const int n0 = blockIdx.x * 128, m0 = blockIdx.y * 128, e = blockIdx.z;

    const int lr = tid >> 1;
    const int lhB = (tid & 1) * 64;
    const __half* aH = A + ((size_t)e * cT + m0 + lr) * K + (lhB >> 1);
    const __half* bH = B + ((size_t)e * Ntot + n0 + lr) * K + (lhB >> 1);
    const uint32_t lrow = (uint32_t)lr * 128u + (uint32_t)lhB;
    const int nK = K / 64;   // 16

    auto load_stage = [&](int s, int k) {
        uint32_t base = smem + s * STAGE_O_B;
        int k0 = k * 64;
#pragma unroll
        for (int j = 0; j < 4; j++) {
            uint32_t sw = SWZ(lrow + j * 16);
            cp16(base          + sw, aH + k0 + j * 8);
            cp16(base + TILE_B + sw, bH + k0 + j * 8);
        }
    };

    const uint32_t arow = (uint32_t)(lane & 15);
    const uint32_t akb  = (uint32_t)((lane >> 4) * 16);
    const uint32_t brow = (uint32_t)((lane & 7) + ((lane & 16) >> 1));
    const uint32_t bkb  = (uint32_t)(((lane & 8) >> 3) * 16);

    float acc[4][4][4] = {};

#pragma unroll
    for (int s = 0; s < STAGES_O; s++) { load_stage(s, s); cp_commit(); }

    for (int kk = 0; kk < nK; kk++) {
        int s = kk % STAGES_O;
        cp_wait<STAGES_O - 1>();
        __syncthreads();
        uint32_t base = smem + s * STAGE_O_B;
#pragma unroll
        for (int ks = 0; ks < 4; ks++) {
            uint32_t Ah[4][4], Bh[2][4];
#pragma unroll
            for (int mt = 0; mt < 4; mt++) {
                uint32_t off = SWZ((uint32_t)(wm + mt * 16 + arow) * 128u + ks * 32 + akb);
                ldsm4(Ah[mt], base + off);
            }
#pragma unroll
            for (int np = 0; np < 2; np++) {
                uint32_t off = SWZ((uint32_t)(wn + np * 16 + brow) * 128u + ks * 32 + bkb);
                ldsm4(Bh[np], base + TILE_B + off);
            }
#pragma unroll
            for (int mt = 0; mt < 4; mt++)
#pragma unroll
                for (int nt = 0; nt < 4; nt++) {
                    int np = nt >> 1, ss = (nt & 1) * 2;
                    mma16816(acc[mt][nt], Ah[mt], Bh[np][ss], Bh[np][ss + 1]);
                }
        }
        __syncthreads();
        if (kk + STAGES_O < nK) load_stage(s, kk + STAGES_O);
        cp_commit();
    }

#pragma unroll
    for (int mt = 0; mt < 4; mt++) {
#pragma unroll
        for (int p = 0; p < 2; p++) {
            int lrow2 = wm + mt * 16 + (lane >> 2) + p * 8;
            size_t gr = ((size_t)e * cT + m0 + lrow2) * (size_t)Ntot;
#pragma unroll
            for (int nt = 0; nt < 4; nt++) {
                int lcol = wn + nt * 8 + (lane & 3) * 2;
                *(float2*)(out + gr + n0 + lcol) =
                    make_float2(acc[mt][nt][p * 2], acc[mt][nt][p * 2 + 1]);
            }
        }
    }
}

// ---------------------------------------------------------------- host
static inline void* symaddr(const void* s) {
    void* p = nullptr;
    cudaGetSymbolAddress(&p, s);
    return p;
}

extern "C" void kernel_launch(void* const* d_in, const int* in_sizes, int n_in,
                              void* d_out, int out_size) {
    (void)in_sizes; (void)n_in; (void)out_size;
    const float* x  = (const float*)d_in[0];
    const float* w1 = (const float*)d_in[1];
    const float* w2 = (const float*)d_in[2];
    const float* w3 = (const float*)d_in[3];
    float* out = (float*)d_out;

    __half* xhi = (__half*)symaddr(g_x_hi);
    __half* xlo = (__half*)symaddr(g_x_lo);
    __half* w1t = (__half*)symaddr(g_w1t);
    __half* w3t = (__half*)symaddr(g_w3t);
    __half* w2t = (__half*)symaddr(g_w2t);
    __half* h   = (__half*)symaddr(g_h);

    cudaFuncSetAttribute(dual_gemm_kernel, cudaFuncAttributeMaxDynamicSharedMemorySize, SMEM_F);
    cudaFuncSetAttribute(out_gemm_kernel, cudaFuncAttributeMaxDynamicSharedMemorySize, SMEM_O);

    // 1) split x into fp16 hi/lo
    cvt_x_kernel<<<(int)(X_ELEMS / 4 / 256), 256>>>((const float4*)x);
    // 2-4) transpose weights to K-major fp16
    cvt_tr_kernel<<<dim3(cH / 32, cD / 32, cE), dim3(32, 8)>>>(w1, 0, cD, cH);
    cvt_tr_kernel<<<dim3(cH / 32, cD / 32, cE), dim3(32, 8)>>>(w3, 1, cD, cH);
    cvt_tr_kernel<<<dim3(cD / 32, cH / 32, cE), dim3(32, 8)>>>(w2, 2, cH, cD);
    // 5) fused: G = x@w1 (hi+lo), U = x@w3 (hi), h = silu(G)*U -> fp16
    dual_gemm_kernel<<<dim3(cH / 128, cT / 128, cE), 256, SMEM_F>>>(
        xhi, xlo, w1t, w3t, h);
    // 6) out = h @ w2 (fp32)
    out_gemm_kernel<<<dim3(cD / 128, cT / 128, cE), 256, SMEM_O>>>(
        h, w2t, out);
}

// round 9
// speedup vs baseline: 2.5967x; 1.2712x over previous
#include <cuda_runtime.h>
#include <cuda_fp16.h>
#include <cstdint>
#include <cstddef>

// ---------------------------------------------------------------- constants
constexpr int cE = 8, cT = 4096, cD = 2048, cH = 1024;
constexpr size_t X_ELEMS = (size_t)cE * cT * cD;
constexpr size_t W_ELEMS = (size_t)cE * cD * cH;
constexpr size_t H_ELEMS = (size_t)cE * cT * cH;

// ---------------------------------------------------------------- scratch
__device__ __align__(16) __half g_x[X_ELEMS];     // [E][T][D] fp16(x)
__device__ __align__(16) __half g_w1t[W_ELEMS];   // [E][H][D] fp16(w1^T)
__device__ __align__(16) __half g_w3t[W_ELEMS];   // [E][H][D] fp16(w3^T)
__device__ __align__(16) __half g_w2t[W_ELEMS];   // [E][D][H] fp16(w2^T)
__device__ __align__(16) __half g_h[H_ELEMS];     // [E][T][H] fp16(h)

// ---------------------------------------------------------------- PTX helpers
__device__ __forceinline__ uint32_t smem_u32(const void* p) {
    return (uint32_t)__cvta_generic_to_shared(p);
}
__device__ __forceinline__ void cp16(uint32_t dst, const void* src) {
    asm volatile("cp.async.cg.shared.global [%0], [%1], 16;"
                 :: "r"(dst), "l"(src) : "memory");
}
__device__ __forceinline__ void cp_commit() {
    asm volatile("cp.async.commit_group;" ::: "memory");
}
template <int N> __device__ __forceinline__ void cp_wait() {
    asm volatile("cp.async.wait_group %0;" :: "n"(N) : "memory");
}
__device__ __forceinline__ void ldsm4(uint32_t* r, uint32_t addr) {
    asm volatile("ldmatrix.sync.aligned.m8n8.x4.shared.b16 {%0,%1,%2,%3}, [%4];"
                 : "=r"(r[0]), "=r"(r[1]), "=r"(r[2]), "=r"(r[3]) : "r"(addr));
}
__device__ __forceinline__ void mma16816(float* d, const uint32_t* a,
                                         uint32_t b0, uint32_t b1) {
    asm volatile(
        "mma.sync.aligned.m16n8k16.row.col.f32.f16.f16.f32 "
        "{%0,%1,%2,%3}, {%4,%5,%6,%7}, {%8,%9}, {%0,%1,%2,%3};"
        : "+f"(d[0]), "+f"(d[1]), "+f"(d[2]), "+f"(d[3])
        : "r"(a[0]), "r"(a[1]), "r"(a[2]), "r"(a[3]), "r"(b0), "r"(b1));
}
#define SWZ(o) ((o) ^ (((o) >> 3) & 0x70))

// ---------------------------------------------------------------- conversions
__global__ void cvt_x_kernel(const float4* __restrict__ x) {
    size_t i = (size_t)blockIdx.x * blockDim.x + threadIdx.x;
    if (i >= X_ELEMS / 4) return;
    float4 v = x[i];
    uint2 o;
    o.x = ((uint32_t)__half_as_ushort(__float2half(v.y)) << 16)
        | __half_as_ushort(__float2half(v.x));
    o.y = ((uint32_t)__half_as_ushort(__float2half(v.w)) << 16)
        | __half_as_ushort(__float2half(v.z));
    ((uint2*)g_x)[i] = o;
}

// transpose: w [E][R][C] f32 -> out [E][C][R] fp16
__global__ void cvt_tr_kernel(const float* __restrict__ w, int which, int R, int C) {
    __shared__ float tile[32][33];
    int e = blockIdx.z;
    int c0 = blockIdx.x * 32, r0 = blockIdx.y * 32;
    int tx = threadIdx.x, ty = threadIdx.y;
    const float* wp = w + (size_t)e * R * C;
#pragma unroll
    for (int i = ty; i < 32; i += 8)
        tile[i][tx] = wp[(size_t)(r0 + i) * C + c0 + tx];
    __syncthreads();
    __half* oh = (which == 0) ? g_w1t : (which == 1) ? g_w3t : g_w2t;
    oh += (size_t)e * C * R;
#pragma unroll
    for (int i = ty; i < 32; i += 8)
        oh[(size_t)(c0 + i) * R + r0 + tx] = __float2half(tile[tx][i]);
}

// ---------------------------------------------------------------- fused dual GEMM
// G = x@w1, U = x@w3 (pure fp16), h = silu(G)*U -> fp16.
constexpr int TILE_B = 128 * 128;            // 128 rows x 128 bytes (64 halfs)
constexpr int STAGES_F = 4;
constexpr int STAGE_F_B = 3 * TILE_B;        // A, B1, B3 = 48 KB
constexpr int SMEM_F = STAGES_F * STAGE_F_B; // 192 KB

__global__ void __launch_bounds__(256, 1) dual_gemm_kernel(
    const __half* __restrict__ A,
    const __half* __restrict__ B1, const __half* __restrict__ B3,
    __half* __restrict__ hout)
{
    constexpr int K = cD, Ntot = cH;
    extern __shared__ __align__(1024) char smraw[];
    const uint32_t smem = smem_u32(smraw);
    const int tid = threadIdx.x;
    const int lane = tid & 31, w = tid >> 5;
    const int wm = (w >> 2) * 64;
    const int wn = (w & 3) * 32;
    const int n0 = blockIdx.x * 128, m0 = blockIdx.y * 128, e = blockIdx.z;

    const int lr = tid >> 1;
    const int lhB = (tid & 1) * 64;
    const __half* aH = A + ((size_t)e * cT + m0 + lr) * K + (lhB >> 1);
    const __half* b1 = B1 + ((size_t)e * Ntot + n0 + lr) * K + (lhB >> 1);
    const __half* b3 = B3 + ((size_t)e * Ntot + n0 + lr) * K + (lhB >> 1);
    const uint32_t lrow = (uint32_t)lr * 128u + (uint32_t)lhB;
    const int nK = K / 64;   // 32

    auto load_stage = [&](int s, int k) {
        uint32_t base = smem + s * STAGE_F_B;
        int k0 = k * 64;
#pragma unroll
        for (int j = 0; j < 4; j++) {
            uint32_t sw = SWZ(lrow + j * 16);
            cp16(base              + sw, aH + k0 + j * 8);
            cp16(base + TILE_B     + sw, b1 + k0 + j * 8);
            cp16(base + 2 * TILE_B + sw, b3 + k0 + j * 8);
        }
    };

    const uint32_t arow = (uint32_t)(lane & 15);
    const uint32_t akb  = (uint32_t)((lane >> 4) * 16);
    const uint32_t brow = (uint32_t)((lane & 7) + ((lane & 16) >> 1));
    const uint32_t bkb  = (uint32_t)(((lane & 8) >> 3) * 16);

    float accG[4][4][4] = {};
    float accU[4][4][4] = {};

#pragma unroll
    for (int s = 0; s < STAGES_F; s++) { load_stage(s, s); cp_commit(); }

    for (int kk = 0; kk < nK; kk++) {
        int s = kk % STAGES_F;
        cp_wait<STAGES_F - 1>();
        __syncthreads();
        uint32_t base = smem + s * STAGE_F_B;
#pragma unroll
        for (int ks = 0; ks < 4; ks++) {
            uint32_t Ah[4][4], Bf[2][4];
#pragma unroll
            for (int mt = 0; mt < 4; mt++) {
                uint32_t off = SWZ((uint32_t)(wm + mt * 16 + arow) * 128u + ks * 32 + akb);
                ldsm4(Ah[mt], base + off);
            }
            // --- G path (w1)
#pragma unroll
            for (int np = 0; np < 2; np++) {
                uint32_t off = SWZ((uint32_t)(wn + np * 16 + brow) * 128u + ks * 32 + bkb);
                ldsm4(Bf[np], base + TILE_B + off);
            }
#pragma unroll
            for (int mt = 0; mt < 4; mt++)
#pragma unroll
                for (int nt = 0; nt < 4; nt++) {
                    int np = nt >> 1, ss = (nt & 1) * 2;
                    mma16816(accG[mt][nt], Ah[mt], Bf[np][ss], Bf[np][ss + 1]);
                }
            // --- U path (w3)
#pragma unroll
            for (int np = 0; np < 2; np++) {
                uint32_t off = SWZ((uint32_t)(wn + np * 16 + brow) * 128u + ks * 32 + bkb);
                ldsm4(Bf[np], base + 2 * TILE_B + off);
            }
#pragma unroll
            for (int mt = 0; mt < 4; mt++)
#pragma unroll
                for (int nt = 0; nt < 4; nt++) {
                    int np = nt >> 1, ss = (nt & 1) * 2;
                    mma16816(accU[mt][nt], Ah[mt], Bf[np][ss], Bf[np][ss + 1]);
                }
        }
        __syncthreads();
        if (kk + STAGES_F < nK) load_stage(s, kk + STAGES_F);
        cp_commit();
    }

    // --- epilogue: h = silu(G) * U -> fp16
#pragma unroll
    for (int mt = 0; mt < 4; mt++) {
#pragma unroll
        for (int p = 0; p < 2; p++) {
            int lrow2 = wm + mt * 16 + (lane >> 2) + p * 8;
            size_t gr = ((size_t)e * cT + m0 + lrow2) * (size_t)Ntot;
#pragma unroll
            for (int nt = 0; nt < 4; nt++) {
                int lcol = wn + nt * 8 + (lane & 3) * 2;
                size_t idx = gr + n0 + lcol;
                float gv0 = accG[mt][nt][p * 2], gv1 = accG[mt][nt][p * 2 + 1];
                float uv0 = accU[mt][nt][p * 2], uv1 = accU[mt][nt][p * 2 + 1];
                float h0 = uv0 * gv0 / (1.0f + __expf(-gv0));
                float h1 = uv1 * gv1 / (1.0f + __expf(-gv1));
                __half2 vh;
                vh.x = __float2half(h0);
                vh.y = __float2half(h1);
                *(__half2*)(hout + idx) = vh;
            }
        }
    }
}

// ---------------------------------------------------------------- out GEMM
// out = h @ w2, pure fp16, fp32 out. 6-stage pipeline.
constexpr int STAGES_O = 6;
constexpr int STAGE_O_B = 2 * TILE_B;        // A, B = 32 KB
constexpr int SMEM_O = STAGES_O * STAGE_O_B; // 192 KB

__global__ void __launch_bounds__(256, 1) out_gemm_kernel(
    const __half* __restrict__ A, const __half* __restrict__ B,
    float* __restrict__ out)
{
    constexpr int K = cH, Ntot = cD;
    extern __shared__ __align__(1024) char smraw[];
    const uint32_t smem = smem_u32(smraw);
    const int tid = threadIdx.x;
    const int lane = tid & 31, w = tid >> 5;
    const int wm = (w >> 2) * 64;
    const int wn = (w & 3) * 32;
    const int n0 = blockIdx.x * 128, m0 = blockIdx.y * 128, e = blockIdx.z;

    const int lr = tid >> 1;
    const int lhB = (tid & 1) * 64;
    const __half* aH = A + ((size_t)e * cT + m0 + lr) * K + (lhB >> 1);
    const __half* bH = B + ((size_t)e * Ntot + n0 + lr) * K + (lhB >> 1);
    const uint32_t lrow = (uint32_t)lr * 128u + (uint32_t)lhB;
    const int nK = K / 64;   // 16

    auto load_stage = [&](int s, int k) {
        uint32_t base = smem + s * STAGE_O_B;
        int k0 = k * 64;
#pragma unroll
        for (int j = 0; j < 4; j++) {
            uint32_t sw = SWZ(lrow + j * 16);
            cp16(base          + sw, aH + k0 + j * 8);
            cp16(base + TILE_B + sw, bH + k0 + j * 8);
        }
    };

    const uint32_t arow = (uint32_t)(lane & 15);
    const uint32_t akb  = (uint32_t)((lane >> 4) * 16);
    const uint32_t brow = (uint32_t)((lane & 7) + ((lane & 16) >> 1));
    const uint32_t bkb  = (uint32_t)(((lane & 8) >> 3) * 16);

    float acc[4][4][4] = {};

#pragma unroll
    for (int s = 0; s < STAGES_O; s++) { load_stage(s, s); cp_commit(); }

    for (int kk = 0; kk < nK; kk++) {
        int s = kk % STAGES_O;
        cp_wait<STAGES_O - 1>();
        __syncthreads();
        uint32_t base = smem + s * STAGE_O_B;
#pragma unroll
        for (int ks = 0; ks < 4; ks++) {
            uint32_t Ah[4][4], Bh[2][4];
#pragma unroll
            for (int mt = 0; mt < 4; mt++) {
                uint32_t off = SWZ((uint32_t)(wm + mt * 16 + arow) * 128u + ks * 32 + akb);
                ldsm4(Ah[mt], base + off);
            }
#pragma unroll
            for (int np = 0; np < 2; np++) {
                uint32_t off = SWZ((uint32_t)(wn + np * 16 + brow) * 128u + ks * 32 + bkb);
                ldsm4(Bh[np], base + TILE_B + off);
            }
#pragma unroll
            for (int mt = 0; mt < 4; mt++)
#pragma unroll
                for (int nt = 0; nt < 4; nt++) {
                    int np = nt >> 1, ss = (nt & 1) * 2;
                    mma16816(acc[mt][nt], Ah[mt], Bh[np][ss], Bh[np][ss + 1]);
                }
        }
        __syncthreads();
        if (kk + STAGES_O < nK) load_stage(s, kk + STAGES_O);
        cp_commit();
    }

#pragma unroll
    for (int mt = 0; mt < 4; mt++) {
#pragma unroll
        for (int p = 0; p < 2; p++) {
            int lrow2 = wm + mt * 16 + (lane >> 2) + p * 8;
            size_t gr = ((size_t)e * cT + m0 + lrow2) * (size_t)Ntot;
#pragma unroll
            for (int nt = 0; nt < 4; nt++) {
                int lcol = wn + nt * 8 + (lane & 3) * 2;
                *(float2*)(out + gr + n0 + lcol) =
                    make_float2(acc[mt][nt][p * 2], acc[mt][nt][p * 2 + 1]);
            }
        }
    }
}

// ---------------------------------------------------------------- host
static inline void* symaddr(const void* s) {
    void* p = nullptr;
    cudaGetSymbolAddress(&p, s);
    return p;
}

extern "C" void kernel_launch(void* const* d_in, const int* in_sizes, int n_in,
                              void* d_out, int out_size) {
    (void)in_sizes; (void)n_in; (void)out_size;
    const float* x  = (const float*)d_in[0];
    const float* w1 = (const float*)d_in[1];
    const float* w2 = (const float*)d_in[2];
    const float* w3 = (const float*)d_in[3];
    float* out = (float*)d_out;

    __half* xh  = (__half*)symaddr(g_x);
    __half* w1t = (__half*)symaddr(g_w1t);
    __half* w3t = (__half*)symaddr(g_w3t);
    __half* w2t = (__half*)symaddr(g_w2t);
    __half* h   = (__half*)symaddr(g_h);

    cudaFuncSetAttribute(dual_gemm_kernel, cudaFuncAttributeMaxDynamicSharedMemorySize, SMEM_F);
    cudaFuncSetAttribute(out_gemm_kernel, cudaFuncAttributeMaxDynamicSharedMemorySize, SMEM_O);

    // 1) x -> fp16
    cvt_x_kernel<<<(int)(X_ELEMS / 4 / 256), 256>>>((const float4*)x);
    // 2-4) transpose weights to K-major fp16
    cvt_tr_kernel<<<dim3(cH / 32, cD / 32, cE), dim3(32, 8)>>>(w1, 0, cD, cH);
    cvt_tr_kernel<<<dim3(cH / 32, cD / 32, cE), dim3(32, 8)>>>(w3, 1, cD, cH);
    cvt_tr_kernel<<<dim3(cD / 32, cH / 32, cE), dim3(32, 8)>>>(w2, 2, cH, cD);
    // 5) fused: G = x@w1, U = x@w3, h = silu(G)*U -> fp16
    dual_gemm_kernel<<<dim3(cH / 128, cT / 128, cE), 256, SMEM_F>>>(
        xh, w1t, w3t, h);
    // 6) out = h @ w2 (fp32)
    out_gemm_kernel<<<dim3(cD / 128, cT / 128, cE), 256, SMEM_O>>>(
        h, w2t, out);
}

// round 10
// speedup vs baseline: 2.6494x; 1.0203x over previous
#include <cuda_runtime.h>
#include <cuda_fp16.h>
#include <cstdint>
#include <cstddef>

// ---------------------------------------------------------------- constants
constexpr int cE = 8, cT = 4096, cD = 2048, cH = 1024;
constexpr size_t X_ELEMS = (size_t)cE * cT * cD;
constexpr size_t W_ELEMS = (size_t)cE * cD * cH;
constexpr size_t H_ELEMS = (size_t)cE * cT * cH;

// ---------------------------------------------------------------- scratch
__device__ __align__(16) __half g_x[X_ELEMS];     // [E][T][D] fp16(x)
__device__ __align__(16) __half g_w1t[W_ELEMS];   // [E][H][D] fp16(w1^T)
__device__ __align__(16) __half g_w3t[W_ELEMS];   // [E][H][D] fp16(w3^T)
__device__ __align__(16) __half g_w2t[W_ELEMS];   // [E][D][H] fp16(w2^T)
__device__ __align__(16) __half g_h[H_ELEMS];     // [E][T][H] fp16(h)

// ---------------------------------------------------------------- PTX helpers
__device__ __forceinline__ uint32_t smem_u32(const void* p) {
    return (uint32_t)__cvta_generic_to_shared(p);
}
__device__ __forceinline__ void cp16(uint32_t dst, const void* src) {
    asm volatile("cp.async.cg.shared.global [%0], [%1], 16;"
                 :: "r"(dst), "l"(src) : "memory");
}
__device__ __forceinline__ void cp_commit() {
    asm volatile("cp.async.commit_group;" ::: "memory");
}
template <int N> __device__ __forceinline__ void cp_wait() {
    asm volatile("cp.async.wait_group %0;" :: "n"(N) : "memory");
}
__device__ __forceinline__ void ldsm4(uint32_t* r, uint32_t addr) {
    asm volatile("ldmatrix.sync.aligned.m8n8.x4.shared.b16 {%0,%1,%2,%3}, [%4];"
                 : "=r"(r[0]), "=r"(r[1]), "=r"(r[2]), "=r"(r[3]) : "r"(addr));
}
__device__ __forceinline__ void mma16816(float* d, const uint32_t* a,
                                         uint32_t b0, uint32_t b1) {
    asm volatile(
        "mma.sync.aligned.m16n8k16.row.col.f32.f16.f16.f32 "
        "{%0,%1,%2,%3}, {%4,%5,%6,%7}, {%8,%9}, {%0,%1,%2,%3};"
        : "+f"(d[0]), "+f"(d[1]), "+f"(d[2]), "+f"(d[3])
        : "r"(a[0]), "r"(a[1]), "r"(a[2]), "r"(a[3]), "r"(b0), "r"(b1));
}
#define SWZ(o) ((o) ^ (((o) >> 3) & 0x70))

// ---------------------------------------------------------------- conversions
__global__ void cvt_x_kernel(const float4* __restrict__ x) {
    size_t i = (size_t)blockIdx.x * blockDim.x + threadIdx.x;
    if (i >= X_ELEMS / 4) return;
    float4 v = x[i];
    uint2 o;
    o.x = ((uint32_t)__half_as_ushort(__float2half(v.y)) << 16)
        | __half_as_ushort(__float2half(v.x));
    o.y = ((uint32_t)__half_as_ushort(__float2half(v.w)) << 16)
        | __half_as_ushort(__float2half(v.z));
    ((uint2*)g_x)[i] = o;
}

// transpose: w [E][R][C] f32 -> out [E][C][R] fp16
__global__ void cvt_tr_kernel(const float* __restrict__ w, int which, int R, int C) {
    __shared__ float tile[32][33];
    int e = blockIdx.z;
    int c0 = blockIdx.x * 32, r0 = blockIdx.y * 32;
    int tx = threadIdx.x, ty = threadIdx.y;
    const float* wp = w + (size_t)e * R * C;
#pragma unroll
    for (int i = ty; i < 32; i += 8)
        tile[i][tx] = wp[(size_t)(r0 + i) * C + c0 + tx];
    __syncthreads();
    __half* oh = (which == 0) ? g_w1t : (which == 1) ? g_w3t : g_w2t;
    oh += (size_t)e * C * R;
#pragma unroll
    for (int i = ty; i < 32; i += 8)
        oh[(size_t)(c0 + i) * R + r0 + tx] = __float2half(tile[tx][i]);
}

// ---------------------------------------------------------------- fused dual GEMM
// G = x@w1, U = x@w3 (pure fp16), h = silu(G)*U -> fp16.
// Single-sync pipeline: wait -> sync -> prefetch freed stage -> compute.
constexpr int TILE_B = 128 * 128;            // 128 rows x 128 bytes (64 halfs)
constexpr int STAGES_F = 4;
constexpr int STAGE_F_B = 3 * TILE_B;        // A, B1, B3 = 48 KB
constexpr int SMEM_F = STAGES_F * STAGE_F_B; // 192 KB

__global__ void __launch_bounds__(256, 1) dual_gemm_kernel(
    const __half* __restrict__ A,
    const __half* __restrict__ B1, const __half* __restrict__ B3,
    __half* __restrict__ hout)
{
    constexpr int K = cD, Ntot = cH;
    extern __shared__ __align__(1024) char smraw[];
    const uint32_t smem = smem_u32(smraw);
    const int tid = threadIdx.x;
    const int lane = tid & 31, w = tid >> 5;
    const int wm = (w >> 2) * 64;
    const int wn = (w & 3) * 32;
    const int n0 = blockIdx.x * 128, m0 = blockIdx.y * 128, e = blockIdx.z;

    const int lr = tid >> 1;
    const int lhB = (tid & 1) * 64;
    const __half* aH = A + ((size_t)e * cT + m0 + lr) * K + (lhB >> 1);
    const __half* b1 = B1 + ((size_t)e * Ntot + n0 + lr) * K + (lhB >> 1);
    const __half* b3 = B3 + ((size_t)e * Ntot + n0 + lr) * K + (lhB >> 1);
    const uint32_t lrow = (uint32_t)lr * 128u + (uint32_t)lhB;
    const int nK = K / 64;   // 32

    auto load_stage = [&](int s, int k) {
        uint32_t base = smem + s * STAGE_F_B;
        int k0 = k * 64;
#pragma unroll
        for (int j = 0; j < 4; j++) {
            uint32_t sw = SWZ(lrow + j * 16);
            cp16(base              + sw, aH + k0 + j * 8);
            cp16(base + TILE_B     + sw, b1 + k0 + j * 8);
            cp16(base + 2 * TILE_B + sw, b3 + k0 + j * 8);
        }
    };

    const uint32_t arow = (uint32_t)(lane & 15);
    const uint32_t akb  = (uint32_t)((lane >> 4) * 16);
    const uint32_t brow = (uint32_t)((lane & 7) + ((lane & 16) >> 1));
    const uint32_t bkb  = (uint32_t)(((lane & 8) >> 3) * 16);

    float accG[4][4][4] = {};
    float accU[4][4][4] = {};

    // prologue: chunks 0..S-2
#pragma unroll
    for (int s = 0; s < STAGES_F - 1; s++) { load_stage(s, s); cp_commit(); }

    for (int kk = 0; kk < nK; kk++) {
        int s = kk % STAGES_F;
        cp_wait<STAGES_F - 2>();   // chunk kk resident
        __syncthreads();           // all warps past chunk kk-1's compute
        // prefetch chunk kk+S-1 into freed stage (kk-1)%S, ahead of compute
        if (kk + STAGES_F - 1 < nK)
            load_stage((kk + STAGES_F - 1) % STAGES_F, kk + STAGES_F - 1);
        cp_commit();
        uint32_t base = smem + s * STAGE_F_B;
#pragma unroll
        for (int ks = 0; ks < 4; ks++) {
            uint32_t Ah[4][4], Bf[2][4];
#pragma unroll
            for (int mt = 0; mt < 4; mt++) {
                uint32_t off = SWZ((uint32_t)(wm + mt * 16 + arow) * 128u + ks * 32 + akb);
                ldsm4(Ah[mt], base + off);
            }
            // --- G path (w1)
#pragma unroll
            for (int np = 0; np < 2; np++) {
                uint32_t off = SWZ((uint32_t)(wn + np * 16 + brow) * 128u + ks * 32 + bkb);
                ldsm4(Bf[np], base + TILE_B + off);
            }
#pragma unroll
            for (int mt = 0; mt < 4; mt++)
#pragma unroll
                for (int nt = 0; nt < 4; nt++) {
                    int np = nt >> 1, ss = (nt & 1) * 2;
                    mma16816(accG[mt][nt], Ah[mt], Bf[np][ss], Bf[np][ss + 1]);
                }
            // --- U path (w3)
#pragma unroll
            for (int np = 0; np < 2; np++) {
                uint32_t off = SWZ((uint32_t)(wn + np * 16 + brow) * 128u + ks * 32 + bkb);
                ldsm4(Bf[np], base + 2 * TILE_B + off);
            }
#pragma unroll
            for (int mt = 0; mt < 4; mt++)
#pragma unroll
                for (int nt = 0; nt < 4; nt++) {
                    int np = nt >> 1, ss = (nt & 1) * 2;
                    mma16816(accU[mt][nt], Ah[mt], Bf[np][ss], Bf[np][ss + 1]);
                }
        }
    }

    // --- epilogue: h = silu(G) * U -> fp16
#pragma unroll
    for (int mt = 0; mt < 4; mt++) {
#pragma unroll
        for (int p = 0; p < 2; p++) {
            int lrow2 = wm + mt * 16 + (lane >> 2) + p * 8;
            size_t gr = ((size_t)e * cT + m0 + lrow2) * (size_t)Ntot;
#pragma unroll
            for (int nt = 0; nt < 4; nt++) {
                int lcol = wn + nt * 8 + (lane & 3) * 2;
                size_t idx = gr + n0 + lcol;
                float gv0 = accG[mt][nt][p * 2], gv1 = accG[mt][nt][p * 2 + 1];
                float uv0 = accU[mt][nt][p * 2], uv1 = accU[mt][nt][p * 2 + 1];
                float h0 = uv0 * gv0 / (1.0f + __expf(-gv0));
                float h1 = uv1 * gv1 / (1.0f + __expf(-gv1));
                __half2 vh;
                vh.x = __float2half(h0);
                vh.y = __float2half(h1);
                *(__half2*)(hout + idx) = vh;
            }
        }
    }
}

// ---------------------------------------------------------------- out GEMM
// out = h @ w2, pure fp16, fp32 out. 3 stages x 32 KB, 2 CTAs/SM.
constexpr int STAGES_O = 3;
constexpr int STAGE_O_B = 2 * TILE_B;        // A, B = 32 KB
constexpr int SMEM_O = STAGES_O * STAGE_O_B; // 96 KB

__global__ void __launch_bounds__(256, 2) out_gemm_kernel(
    const __half* __restrict__ A, const __half* __restrict__ B,
    float* __restrict__ out)
{
    constexpr int K = cH, Ntot = cD;
    extern __shared__ __align__(1024) char smraw[];
    const uint32_t smem = smem_u32(smraw);
    const int tid = threadIdx.x;
    const int lane = tid & 31, w = tid >> 5;
    const int wm = (w >> 2) * 64;
    const int wn = (w & 3) * 32;
    const int n0 = blockIdx.x * 128, m0 = blockIdx.y * 128, e = blockIdx.z;

    const int lr = tid >> 1;
    const int lhB = (tid & 1) * 64;
    const __half* aH = A + ((size_t)e * cT + m0 + lr) * K + (lhB >> 1);
    const __half* bH = B + ((size_t)e * Ntot + n0 + lr) * K + (lhB >> 1);
    const uint32_t lrow = (uint32_t)lr * 128u + (uint32_t)lhB;
    const int nK = K / 64;   // 16

    auto load_stage = [&](int s, int k) {
        uint32_t base = smem + s * STAGE_O_B;
        int k0 = k * 64;
#pragma unroll
        for (int j = 0; j < 4; j++) {
            uint32_t sw = SWZ(lrow + j * 16);
            cp16(base          + sw, aH + k0 + j * 8);
            cp16(base + TILE_B + sw, bH + k0 + j * 8);
        }
    };

    const uint32_t arow = (uint32_t)(lane & 15);
    const uint32_t akb  = (uint32_t)((lane >> 4) * 16);
    const uint32_t brow = (uint32_t)((lane & 7) + ((lane & 16) >> 1));
    const uint32_t bkb  = (uint32_t)(((lane & 8) >> 3) * 16);

    float acc[4][4][4] = {};

#pragma unroll
    for (int s = 0; s < STAGES_O - 1; s++) { load_stage(s, s); cp_commit(); }

    for (int kk = 0; kk < nK; kk++) {
        int s = kk % STAGES_O;
        cp_wait<STAGES_O - 2>();
        __syncthreads();
        if (kk + STAGES_O - 1 < nK)
            load_stage((kk + STAGES_O - 1) % STAGES_O, kk + STAGES_O - 1);
        cp_commit();
        uint32_t base = smem + s * STAGE_O_B;
#pragma unroll
        for (int ks = 0; ks < 4; ks++) {
            uint32_t Ah[4][4], Bh[2][4];
#pragma unroll
            for (int mt = 0; mt < 4; mt++) {
                uint32_t off = SWZ((uint32_t)(wm + mt * 16 + arow) * 128u + ks * 32 + akb);
                ldsm4(Ah[mt], base + off);
            }
#pragma unroll
            for (int np = 0; np < 2; np++) {
                uint32_t off = SWZ((uint32_t)(wn + np * 16 + brow) * 128u + ks * 32 + bkb);
                ldsm4(Bh[np], base + TILE_B + off);
            }
#pragma unroll
            for (int mt = 0; mt < 4; mt++)
#pragma unroll
                for (int nt = 0; nt < 4; nt++) {
                    int np = nt >> 1, ss = (nt & 1) * 2;
                    mma16816(acc[mt][nt], Ah[mt], Bh[np][ss], Bh[np][ss + 1]);
                }
        }
    }

#pragma unroll
    for (int mt = 0; mt < 4; mt++) {
#pragma unroll
        for (int p = 0; p < 2; p++) {
            int lrow2 = wm + mt * 16 + (lane >> 2) + p * 8;
            size_t gr = ((size_t)e * cT + m0 + lrow2) * (size_t)Ntot;
#pragma unroll
            for (int nt = 0; nt < 4; nt++) {
                int lcol = wn + nt * 8 + (lane & 3) * 2;
                *(float2*)(out + gr + n0 + lcol) =
                    make_float2(acc[mt][nt][p * 2], acc[mt][nt][p * 2 + 1]);
            }
        }
    }
}

// ---------------------------------------------------------------- host
static inline void* symaddr(const void* s) {
    void* p = nullptr;
    cudaGetSymbolAddress(&p, s);
    return p;
}

extern "C" void kernel_launch(void* const* d_in, const int* in_sizes, int n_in,
                              void* d_out, int out_size) {
    (void)in_sizes; (void)n_in; (void)out_size;
    const float* x  = (const float*)d_in[0];
    const float* w1 = (const float*)d_in[1];
    const float* w2 = (const float*)d_in[2];
    const float* w3 = (const float*)d_in[3];
    float* out = (float*)d_out;

    __half* xh  = (__half*)symaddr(g_x);
    __half* w1t = (__half*)symaddr(g_w1t);
    __half* w3t = (__half*)symaddr(g_w3t);
    __half* w2t = (__half*)symaddr(g_w2t);
    __half* h   = (__half*)symaddr(g_h);

    cudaFuncSetAttribute(dual_gemm_kernel, cudaFuncAttributeMaxDynamicSharedMemorySize, SMEM_F);
    cudaFuncSetAttribute(out_gemm_kernel, cudaFuncAttributeMaxDynamicSharedMemorySize, SMEM_O);

    // 1) x -> fp16
    cvt_x_kernel<<<(int)(X_ELEMS / 4 / 256), 256>>>((const float4*)x);
    // 2-4) transpose weights to K-major fp16
    cvt_tr_kernel<<<dim3(cH / 32, cD / 32, cE), dim3(32, 8)>>>(w1, 0, cD, cH);
    cvt_tr_kernel<<<dim3(cH / 32, cD / 32, cE), dim3(32, 8)>>>(w3, 1, cD, cH);
    cvt_tr_kernel<<<dim3(cD / 32, cH / 32, cE), dim3(32, 8)>>>(w2, 2, cH, cD);
    // 5) fused: G = x@w1, U = x@w3, h = silu(G)*U -> fp16
    dual_gemm_kernel<<<dim3(cH / 128, cT / 128, cE), 256, SMEM_F>>>(
        xh, w1t, w3t, h);
    // 6) out = h @ w2 (fp32)
    out_gemm_kernel<<<dim3(cD / 128, cT / 128, cE), 256, SMEM_O>>>(
        h, w2t, out);
}